// round 1
// baseline (speedup 1.0000x reference)
#include <cuda_runtime.h>

// ENC_GRUTurbo: fused 2-layer minGRU x2 networks + global layernorm.
// B=256, L=2048, H=64. One CTA per (batch, network). fp32 with packed f32x2 FMA.

#define BB 256
#define LL 2048
#define HH 64
#define TT 64
#define NCHUNK (LL / TT)
#define NTOT (BB * LL * 2)

typedef unsigned long long ull;

__device__ double g_sum;
__device__ double g_sumsq;

__device__ __forceinline__ ull fma2(ull a, ull b, ull c) {
    ull d;
    asm("fma.rn.f32x2 %0, %1, %2, %3;" : "=l"(d) : "l"(a), "l"(b), "l"(c));
    return d;
}
__device__ __forceinline__ ull pack2(float x, float y) {
    ull d;
    asm("mov.b64 %0, {%1, %2};" : "=l"(d) : "f"(x), "f"(y));
    return d;
}
__device__ __forceinline__ float2 unpack2(ull v) {
    float x, y;
    asm("mov.b64 {%0, %1}, %2;" : "=f"(x), "=f"(y) : "l"(v));
    return make_float2(x, y);
}
__device__ __forceinline__ float sigmoidf(float x) {
    return 1.0f / (1.0f + __expf(-x));
}

struct Params {
    const float* inputs;   // [B*L]
    const int*   p;        // [L]
    const float* w[20];    // net0: wz0,bz0,wh0,bh0,wz1,bz1,wh1,bh1,wo,bo ; net1: same
    float*       out;      // [B*L*2]
};

struct Smem {
    float2 W[HH * HH];       // interleaved (wz1, wh1), [c][j]
    float  h0T[HH][TT + 2];  // time-transposed h0, padded (stride 66)
    float  bufA[TT * HH];    // a-coeffs / products, [t][c]
    float  bufB[TT * HH];    // b-coeffs, [t][c]
    float  xs[TT];
    float  wz0[HH], bz0[HH], wh0[HH], bh0[HH];
    float  bz1[HH], bh1[HH], wo[HH];
    float  bo;
    float  red[128];
};

__global__ void zero_accum_kernel() {
    g_sum = 0.0;
    g_sumsq = 0.0;
}

__global__ void __launch_bounds__(256, 2) gru_main_kernel(Params prm) {
    extern __shared__ char smem_raw[];
    Smem* s = (Smem*)smem_raw;

    const int tid = threadIdx.x;
    const int b   = blockIdx.x >> 1;
    const int net = blockIdx.x & 1;

    const float* const* w = prm.w + net * 10;
    const float* wz1 = w[4];
    const float* wh1 = w[6];

    // ---- load weights to SMEM ----
    for (int i = tid; i < HH * HH; i += 256) {
        s->W[i] = make_float2(wz1[i], wh1[i]);
    }
    if (tid < HH) {
        s->wz0[tid] = w[0][tid];
        s->bz0[tid] = w[1][tid];
        s->wh0[tid] = w[2][tid];
        s->bh0[tid] = w[3][tid];
        s->bz1[tid] = w[5][tid];
        s->bh1[tid] = w[7][tid];
        s->wo[tid]  = w[8][tid];
    }
    if (tid == 0) s->bo = w[9][0];

    // first x chunk (gather through p for net 1)
    if (tid < TT) {
        int t = tid;
        int src = net ? prm.p[t] : t;
        s->xs[tid] = prm.inputs[(size_t)b * LL + src];
    }
    __syncthreads();

    float h0c = 0.0f, h1c = 0.0f;   // scan carries (threads < 64)
    float lsum = 0.0f, lsumsq = 0.0f;

    const int j  = tid & 63;
    const int tg = tid >> 6;
    const int tb = tg * 16;

    for (int k = 0; k < NCHUNK; ++k) {
        // ---- phase a: layer-0 elementwise a0,b0 -> bufA/bufB ----
        #pragma unroll
        for (int i = 0; i < (TT * HH) / 256; ++i) {
            int e = i * 256 + tid;
            int t = e >> 6;
            int c = e & 63;
            float xv = s->xs[t];
            float z  = sigmoidf(fmaf(xv, s->wz0[c], s->bz0[c]));
            float ht = fmaf(xv, s->wh0[c], s->bh0[c]);
            s->bufA[e] = 1.0f - z;
            s->bufB[e] = z * ht;
        }
        __syncthreads();

        // ---- phase b: layer-0 scan -> h0T (transposed) ----
        if (tid < HH) {
            float h = h0c;
            #pragma unroll 4
            for (int t = 0; t < TT; ++t) {
                h = fmaf(s->bufA[t * HH + tid], h, s->bufB[t * HH + tid]);
                s->h0T[tid][t] = h;
            }
            h0c = h;
        }
        __syncthreads();

        // ---- phase c: layer-1 matvec (z1, htil1) with packed f32x2 ----
        {
            ull az[8], ah[8];
            ull bz2 = pack2(s->bz1[j], s->bz1[j]);
            ull bh2 = pack2(s->bh1[j], s->bh1[j]);
            #pragma unroll
            for (int p = 0; p < 8; ++p) { az[p] = bz2; ah[p] = bh2; }

            #pragma unroll 4
            for (int c = 0; c < HH; ++c) {
                float2 wv = s->W[c * HH + j];
                ull wz2 = pack2(wv.x, wv.x);
                ull wh2 = pack2(wv.y, wv.y);
                const ull* hp = (const ull*)&s->h0T[c][tb];
                #pragma unroll
                for (int p = 0; p < 8; ++p) {
                    ull h2u = hp[p];       // (h0[t], h0[t+1]) broadcast LDS.64
                    az[p] = fma2(h2u, wz2, az[p]);
                    ah[p] = fma2(h2u, wh2, ah[p]);
                }
            }
            #pragma unroll
            for (int p = 0; p < 8; ++p) {
                float2 zz = unpack2(az[p]);
                float2 hh = unpack2(ah[p]);
                float z0v = sigmoidf(zz.x);
                float z1v = sigmoidf(zz.y);
                int t0i = tb + 2 * p;
                s->bufA[t0i * HH + j]       = 1.0f - z0v;
                s->bufB[t0i * HH + j]       = z0v * hh.x;
                s->bufA[(t0i + 1) * HH + j] = 1.0f - z1v;
                s->bufB[(t0i + 1) * HH + j] = z1v * hh.y;
            }
        }
        __syncthreads();

        // ---- phase d: layer-1 scan + Wo product (into bufA) ----
        if (tid < HH) {
            float h  = h1c;
            float wv = s->wo[tid];
            #pragma unroll 4
            for (int t = 0; t < TT; ++t) {
                float a = s->bufA[t * HH + tid];
                float bb2 = s->bufB[t * HH + tid];
                h = fmaf(a, h, bb2);
                s->bufA[t * HH + tid] = h * wv;
            }
            h1c = h;
        }
        __syncthreads();

        // ---- phase e: output reduce (threads<64), prefetch next x (64..127) ----
        if (tid < TT) {
            float ssum = s->bo;
            #pragma unroll 4
            for (int i = 0; i < HH; ++i) {
                int c = (tid + i) & 63;      // rotated: conflict-free
                ssum += s->bufA[tid * HH + c];
            }
            int t_glob = k * TT + tid;
            prm.out[((size_t)b * LL + t_glob) * 2 + net] = ssum;
            lsum   += ssum;
            lsumsq += ssum * ssum;
        } else if (tid < 64 + TT) {
            if (k + 1 < NCHUNK) {
                int t = tid - 64;
                int tg2 = (k + 1) * TT + t;
                int src = net ? prm.p[tg2] : tg2;
                s->xs[t] = prm.inputs[(size_t)b * LL + src];
            }
        }
        __syncthreads();
    }

    // ---- per-CTA reduction of sum / sumsq ----
    if (tid < 64) {
        s->red[tid]      = lsum;
        s->red[64 + tid] = lsumsq;
    }
    __syncthreads();
    if (tid == 0) {
        float ts = 0.0f, tq = 0.0f;
        #pragma unroll 4
        for (int i = 0; i < 64; ++i) { ts += s->red[i]; tq += s->red[64 + i]; }
        atomicAdd(&g_sum,   (double)ts);
        atomicAdd(&g_sumsq, (double)tq);
    }
}

__global__ void normalize_kernel(float* out) {
    const double n = (double)NTOT;
    double mean = g_sum / n;
    double var  = (g_sumsq - n * mean * mean) / (n - 1.0);
    float m  = (float)mean;
    float rs = (float)(1.0 / sqrt(var));
    int i = blockIdx.x * blockDim.x + threadIdx.x;
    if (i < NTOT) {
        out[i] = (out[i] - m) * rs;
    }
}

extern "C" void kernel_launch(void* const* d_in, const int* in_sizes, int n_in,
                              void* d_out, int out_size) {
    (void)in_sizes; (void)n_in; (void)out_size;

    Params prm;
    prm.inputs = (const float*)d_in[0];
    prm.p      = (const int*)d_in[1];
    for (int i = 0; i < 20; ++i) {
        prm.w[i] = (const float*)d_in[2 + i];
    }
    prm.out = (float*)d_out;

    static bool attr_set = false;
    size_t smem = sizeof(Smem);
    // cudaFuncSetAttribute is not a stream op; safe under graph capture.
    cudaFuncSetAttribute(gru_main_kernel,
                         cudaFuncAttributeMaxDynamicSharedMemorySize, (int)smem);
    (void)attr_set;

    zero_accum_kernel<<<1, 1>>>();
    gru_main_kernel<<<BB * 2, 256, smem>>>(prm);
    normalize_kernel<<<(NTOT + 255) / 256, 256>>>((float*)d_out);
}